// round 12
// baseline (speedup 1.0000x reference)
#include <cuda_runtime.h>
#include <math.h>

#define NNODE 50000
#define VOCABN 401
#define NQ 64
#define EB 96
#define VSTRIDE 100

// ---------------- scratch (device globals: no allocation allowed) -------------
__device__ int   g_is64;                                   // index dtype flag (edges/q_rel)
__device__ __align__(16) float g_NG[NNODE * 256];          // hidden @ G3^T
__device__ __align__(16) float g_NW[NNODE * 64];           // hidden @ Ws^T
__device__ __align__(16) float g_RG[VOCABN * 256];         // rela @ G1^T
__device__ __align__(16) float g_RH[VOCABN * 128];         // rela @ H1^T + ht_b
__device__ __align__(16) float g_RW[VOCABN * 64];          // rela @ Wr^T
__device__ __align__(16) float g_QG[NQ * 256];             // hqr @ G2^T + gate_b
__device__ __align__(16) float g_QW[NQ * 64];              // hqr @ Wqr^T + Wqr_b
__device__ __align__(16) float g_GWT[384 * 256];           // gateW^T [c][j]
__device__ __align__(16) float g_HTT[256 * 128];           // ht_W^T  [c][j] (rows 128.. = H2T)
__device__ __align__(16) float g_WsT[128 * 64];
__device__ __align__(16) float g_WrT[128 * 64];
__device__ __align__(16) float g_WqrT[128 * 64];
__device__ __align__(16) float g_WhT[128 * 128];
__device__ __align__(16) float g_agg[NNODE * 128];
__device__ float g_deg[NNODE];

// Fast-math-independent transcendentals: force the MUFU path regardless of
// harness nvcc flags. __expf err ~1e-7 rel; both forms degrade gracefully
// (exp->inf => sigmoid->1, tanh->1; exp->0 => sigmoid->0, tanh->-1).
__device__ __forceinline__ float sigmoidf_(float x) {
    return __fdividef(1.f, 1.f + __expf(-x));
}
__device__ __forceinline__ float tanhf_(float x) {
    float t = __expf(2.f * x);
    return 1.f - __fdividef(2.f, t + 1.f);
}

// ---- packed f32x2 helpers (fma.rn.f32x2: sm_100+ only, 2x fp32 FMA rate) ----
typedef unsigned long long ull;
__device__ __forceinline__ void fma2(ull& acc, ull a, ull b) {
    asm("fma.rn.f32x2 %0, %1, %2, %0;" : "+l"(acc) : "l"(a), "l"(b));
}
__device__ __forceinline__ ull pack2(float x, float y) {
    ull r; asm("mov.b64 %0, {%1, %2};" : "=l"(r) : "f"(x), "f"(y)); return r;
}
__device__ __forceinline__ float2 unpack2(ull v) {
    float2 r; asm("mov.b64 {%0, %1}, %2;" : "=f"(r.x), "=f"(r.y) : "l"(v)); return r;
}
// Fire-and-forget global float add (guaranteed REDG, no return round-trip).
__device__ __forceinline__ void red_add(float* p, float v) {
    asm volatile("red.global.add.f32 [%0], %1;" :: "l"(p), "f"(v) : "memory");
}

// ---------------- setup: dtype detect + zero + weight transposes ----------------
// Detection: int64 edges => every odd 32-bit word is a zero high-word (values <
// 2^31). int32 edges => odd flat words alternate onto cols {1,3,5}/{0,2,4,6} by
// row parity; obj/rel/sub values guarantee a nonzero within the first 293 rows.
__global__ void k_setup(const int* __restrict__ ew,
                        const float* __restrict__ gateW, const float* __restrict__ htW,
                        const float* __restrict__ Ws, const float* __restrict__ Wr,
                        const float* __restrict__ Wqr, const float* __restrict__ Wh) {
    if (blockIdx.x == 0) {
        __shared__ int any;
        if (threadIdx.x == 0) any = 0;
        __syncthreads();
        for (int i = threadIdx.x; i < 1024; i += blockDim.x)
            if (ew[2 * i + 1] != 0) any = 1;
        __syncthreads();
        if (threadIdx.x == 0) g_is64 = (any == 0) ? 1 : 0;
    }
    int i0 = blockIdx.x * blockDim.x + threadIdx.x;
    int st = gridDim.x * blockDim.x;
    for (int i = i0; i < NNODE * 128; i += st) g_agg[i] = 0.f;
    for (int i = i0; i < NNODE; i += st) g_deg[i] = 0.f;
    for (int x = i0; x < 384 * 256; x += st) { int c = x >> 8, j = x & 255; g_GWT[x] = gateW[j * 384 + c]; }
    for (int x = i0; x < 256 * 128; x += st) { int c = x >> 7, j = x & 127; g_HTT[x] = htW[j * 256 + c]; }
    for (int x = i0; x < 128 * 64;  x += st) { int k = x >> 6, j = x & 63;
        g_WsT[x] = Ws[j * 128 + k]; g_WrT[x] = Wr[j * 128 + k]; g_WqrT[x] = Wqr[j * 128 + k]; }
    for (int x = i0; x < 128 * 128; x += st) { int k = x >> 7, j = x & 127; g_WhT[x] = Wh[j * 128 + k]; }
}

// ------- merged per-vocab (blocks 0..400) + per-query (blocks 401..464) --------
__global__ void k_pre(const float* __restrict__ rela, const float* __restrict__ htb,
                      const void* __restrict__ q_rel, const float* __restrict__ gb,
                      const float* __restrict__ wqrb) {
    __shared__ float row[128];
    int tid = threadIdx.x;
    if (blockIdx.x < VOCABN) {
        int v = blockIdx.x;
        row[tid] = rela[v * 128 + tid];
        __syncthreads();
        float a0 = 0.f, a1 = 0.f, ah = htb[tid];
        #pragma unroll 4
        for (int k = 0; k < 128; k++) {
            float x = row[k];
            a0 += x * g_GWT[k * 256 + tid];
            a1 += x * g_GWT[k * 256 + 128 + tid];
            ah += x * g_HTT[k * 128 + tid];
        }
        g_RG[v * 256 + tid] = a0;
        g_RG[v * 256 + 128 + tid] = a1;
        g_RH[v * 128 + tid] = ah;
        if (tid < 64) {
            float aw = 0.f;
            #pragma unroll 4
            for (int k = 0; k < 128; k++) aw += row[k] * g_WrT[k * 64 + tid];
            g_RW[v * 64 + tid] = aw;
        }
    } else {
        int r = blockIdx.x - VOCABN;
        int q = g_is64 ? (int)((const long long*)q_rel)[r] : ((const int*)q_rel)[r];
        row[tid] = rela[q * 128 + tid];
        __syncthreads();
        float a0 = gb[tid], a1 = gb[128 + tid];
        #pragma unroll 4
        for (int k = 0; k < 128; k++) {
            float x = row[k];
            a0 += x * g_GWT[(128 + k) * 256 + tid];
            a1 += x * g_GWT[(128 + k) * 256 + 128 + tid];
        }
        g_QG[r * 256 + tid] = a0;
        g_QG[r * 256 + 128 + tid] = a1;
        if (tid < 64) {
            float aw = wqrb[tid];
            #pragma unroll 4
            for (int k = 0; k < 128; k++) aw += row[k] * g_WqrT[k * 64 + tid];
            g_QW[r * 64 + tid] = aw;
        }
    }
}

// ------- per-node precompute: NG = hidden@G3^T, NW = hidden@Ws^T ---------------
// 4 nodes per warp: one weight-row load per k feeds 4 nodes => 4x less L1/weight
// traffic (was the binding constraint at 1 node/warp). 32 nodes per 256-thr block.
__global__ void __launch_bounds__(256) k_node(const float* __restrict__ hidden) {
    __shared__ float sx[32][128];
    int tid = threadIdx.x;
    int w = tid >> 5, lane = tid & 31;
    int nbase = blockIdx.x * 32;
    // stage 32 node rows (guard tail)
    for (int i = tid; i < 32 * 32; i += 256) {
        int nn = i >> 5, q = i & 31;
        if (nbase + nn < NNODE)
            *(float4*)&sx[nn][q * 4] = *(const float4*)&hidden[(size_t)(nbase + nn) * 128 + q * 4];
    }
    __syncthreads();
    int n0 = w * 4;   // local node base for this warp
    ull acc[4][5];
    #pragma unroll
    for (int g = 0; g < 4; g++)
        #pragma unroll
        for (int a = 0; a < 5; a++) acc[g][a] = 0ull;

    for (int k4 = 0; k4 < 32; k4++) {
        float4 xq[4];
        #pragma unroll
        for (int g = 0; g < 4; g++) xq[g] = *(const float4*)&sx[n0 + g][k4 * 4];
        #pragma unroll
        for (int kk = 0; kk < 4; kk++) {
            int k = k4 * 4 + kk;
            ulonglong2 g0 = *(const ulonglong2*)&g_GWT[(256 + k) * 256 + lane * 4];
            ulonglong2 g1 = *(const ulonglong2*)&g_GWT[(256 + k) * 256 + 128 + lane * 4];
            ull ws = *(const ull*)&g_WsT[k * 64 + lane * 2];
            #pragma unroll
            for (int g = 0; g < 4; g++) {
                float x = (&xq[g].x)[kk];
                ull xx = pack2(x, x);
                fma2(acc[g][0], xx, g0.x); fma2(acc[g][1], xx, g0.y);
                fma2(acc[g][2], xx, g1.x); fma2(acc[g][3], xx, g1.y);
                fma2(acc[g][4], xx, ws);
            }
        }
    }
    #pragma unroll
    for (int g = 0; g < 4; g++) {
        int n = nbase + n0 + g;
        if (n < NNODE) {
            *(ulonglong2*)&g_NG[(size_t)n * 256 + lane * 4]       = make_ulonglong2(acc[g][0], acc[g][1]);
            *(ulonglong2*)&g_NG[(size_t)n * 256 + 128 + lane * 4] = make_ulonglong2(acc[g][2], acc[g][3]);
            *(ull*)&g_NW[(size_t)n * 64 + lane * 2] = acc[g][4];
        }
    }
}

// ---------------- fused edge kernel ---------------------------------------------
// EB=96, ~100 KB smem => 2 CTAs/SM: one CTA's Phase-A gather (L2-bound) overlaps
// the other's Phase-B GEMM (FMA-bound). B-operand H2T is read straight from
// global: per-k 512B row shared by all 6 GEMM warps => L1-resident hot window.
// Phase A: 8 warps x 3 groups of 4 edges: 12 independent gathers in flight,
//          V stored via STS.128 across the 4-edge group (conflict-free).
// Phase B: 96x128x128 GEMM with fma.rn.f32x2, 192 threads, 8x8 register tiles.
// Phase C: tanh + GRU blend + sigmoid(alpha) scale + red.global.add.v4 scatter.
__global__ void __launch_bounds__(256, 2)
k_edge(const void* __restrict__ edges, const float* __restrict__ hidden,
       const float* __restrict__ walpha, long long nE) {
    extern __shared__ float smem[];
    float* sVT  = smem;                       // [128 k][VSTRIDE] V^T (padded e stride)
    float* sU   = sVT + 128 * VSTRIDE;        // [96 e][128 k] update gate
    int*   sIdx = (int*)(sU + EB * 128);      // [96 e][4] = {ridx, rel, sub, obj}
    float* sSig = (float*)(sIdx + EB * 4);    // [96 e]
    float* sWa  = sSig + EB;                  // [64] walpha staged

    int tid = threadIdx.x;
    long long base = (long long)blockIdx.x * EB;
    int is64 = g_is64;

    if (tid < 64) sWa[tid] = walpha[tid];
    // cooperative edge-index load
    for (int i = tid; i < EB * 4; i += 256) {
        int e = i >> 2, f = i & 3;
        long long ge = base + e;
        int v;
        if (ge < nE) {
            int col = (f == 0) ? 0 : (f == 1) ? 2 : (f == 2) ? 4 : 5;
            if (is64) v = (int)((const long long*)edges)[ge * 7 + col];
            else      v = ((const int*)edges)[ge * 7 + col];
        } else v = (f == 3) ? -1 : 0;
        sIdx[i] = v;
    }
    __syncthreads();

    int w = tid >> 5, lane = tid & 31;
    #pragma unroll
    for (int g4 = 0; g4 < 3; g4++) {
        int e0 = w * 12 + g4 * 4;
        int ridx[4], rel[4], sub[4], obj[4];
        #pragma unroll
        for (int g = 0; g < 4; g++) {
            ridx[g] = sIdx[(e0 + g) * 4 + 0];
            rel[g]  = sIdx[(e0 + g) * 4 + 1];
            sub[g]  = sIdx[(e0 + g) * 4 + 2];
            obj[g]  = sIdx[(e0 + g) * 4 + 3];
        }
        float ap[4] = {0.f, 0.f, 0.f, 0.f};
        #pragma unroll
        for (int p = 0; p < 4; p++) {
            int k = p * 32 + lane;
            float4 v;
            float* vv = &v.x;
            #pragma unroll
            for (int g = 0; g < 4; g++) {
                if (obj[g] >= 0) {
                    float gu = g_NG[sub[g] * 256 + k]       + g_RG[rel[g] * 256 + k]       + g_QG[ridx[g] * 256 + k];
                    float gr = g_NG[sub[g] * 256 + 128 + k] + g_RG[rel[g] * 256 + 128 + k] + g_QG[ridx[g] * 256 + 128 + k];
                    float u  = sigmoidf_(gu);
                    float r  = sigmoidf_(gr);
                    float hs = hidden[sub[g] * 128 + k];
                    vv[g] = r * hs;
                    sU[(e0 + g) * 128 + k] = u;
                    if (p < 2) {
                        float pre = g_NW[sub[g] * 64 + k] + g_RW[rel[g] * 64 + k] + g_QW[ridx[g] * 64 + k];
                        float lr = pre > 0.f ? pre : 0.01f * pre;
                        ap[g] += lr * sWa[k];
                    }
                } else {
                    vv[g] = 0.f;
                    sU[(e0 + g) * 128 + k] = 0.f;
                }
            }
            *(float4*)&sVT[k * VSTRIDE + e0] = v;   // conflict-free STS.128
        }
        #pragma unroll
        for (int g = 0; g < 4; g++) {
            #pragma unroll
            for (int o = 16; o; o >>= 1) ap[g] += __shfl_xor_sync(0xffffffffu, ap[g], o);
        }
        if (lane == 0) {
            #pragma unroll
            for (int g = 0; g < 4; g++) {
                if (obj[g] >= 0) {
                    sSig[e0 + g] = sigmoidf_(ap[g]);
                    red_add(&g_deg[obj[g]], 1.f);
                } else sSig[e0 + g] = 0.f;
            }
        }
    }
    __syncthreads();

    if (tid < 192) {
        // Phase B: candpre[e][j] = sum_k V[e][k] * H2T[k][j]
        // 16 tx (j) x 12 ty (e), 8x8 tile per thread. B from global (L1/L2 hot).
        int tx = tid & 15, ty = tid >> 4;
        int j0 = tx * 8, e0 = ty * 8;
        const float* H2T = g_HTT + 128 * 128;
        ull accp[8][4];
        #pragma unroll
        for (int i = 0; i < 8; i++)
            #pragma unroll
            for (int j = 0; j < 4; j++) accp[i][j] = 0ull;

        #pragma unroll 4
        for (int k = 0; k < 128; k++) {
            ulonglong2 b01 = *(const ulonglong2*)&H2T[k * 128 + j0];
            ulonglong2 b23 = *(const ulonglong2*)&H2T[k * 128 + j0 + 4];
            float4 a0 = *(const float4*)&sVT[k * VSTRIDE + e0];
            float4 a1 = *(const float4*)&sVT[k * VSTRIDE + e0 + 4];
            float av[8] = {a0.x, a0.y, a0.z, a0.w, a1.x, a1.y, a1.z, a1.w};
            #pragma unroll
            for (int i = 0; i < 8; i++) {
                ull a2 = pack2(av[i], av[i]);
                fma2(accp[i][0], a2, b01.x);
                fma2(accp[i][1], a2, b01.y);
                fma2(accp[i][2], a2, b23.x);
                fma2(accp[i][3], a2, b23.y);
            }
        }

        // Phase C
        #pragma unroll
        for (int i = 0; i < 8; i++) {
            int e = e0 + i;
            int obj = sIdx[e * 4 + 3];
            if (obj < 0) continue;
            int rel = sIdx[e * 4 + 1], sub = sIdx[e * 4 + 2];
            float sg = sSig[e];
            #pragma unroll
            for (int h = 0; h < 2; h++) {
                int j = j0 + h * 4;
                float2 c0 = unpack2(accp[i][h * 2]);
                float2 c1 = unpack2(accp[i][h * 2 + 1]);
                float4 rh = *(const float4*)&g_RH[rel * 128 + j];
                float4 hv = *(const float4*)&hidden[sub * 128 + j];
                float4 uv = *(const float4*)&sU[e * 128 + j];
                float o0 = sg * ((1.f - uv.x) * hv.x + uv.x * tanhf_(c0.x + rh.x));
                float o1 = sg * ((1.f - uv.y) * hv.y + uv.y * tanhf_(c0.y + rh.y));
                float o2 = sg * ((1.f - uv.z) * hv.z + uv.z * tanhf_(c1.x + rh.z));
                float o3 = sg * ((1.f - uv.w) * hv.w + uv.w * tanhf_(c1.y + rh.w));
                float* p = g_agg + (size_t)obj * 128 + j;
                asm volatile("red.global.add.v4.f32 [%0], {%1,%2,%3,%4};"
                             :: "l"(p), "f"(o0), "f"(o1), "f"(o2), "f"(o3) : "memory");
            }
        }
    }
}

// ------- final: out = (agg @ Wh^T) / sqrt(deg+1e-4), 4 nodes per warp -----------
__global__ void __launch_bounds__(256) k_final(float* __restrict__ out) {
    __shared__ float sx[32][128];
    int tid = threadIdx.x;
    int w = tid >> 5, lane = tid & 31;
    int nbase = blockIdx.x * 32;
    for (int i = tid; i < 32 * 32; i += 256) {
        int nn = i >> 5, q = i & 31;
        if (nbase + nn < NNODE)
            *(float4*)&sx[nn][q * 4] = *(const float4*)&g_agg[(size_t)(nbase + nn) * 128 + q * 4];
    }
    __syncthreads();
    int n0 = w * 4;
    ull acc[4][2];
    #pragma unroll
    for (int g = 0; g < 4; g++) { acc[g][0] = 0ull; acc[g][1] = 0ull; }

    for (int k4 = 0; k4 < 32; k4++) {
        float4 xq[4];
        #pragma unroll
        for (int g = 0; g < 4; g++) xq[g] = *(const float4*)&sx[n0 + g][k4 * 4];
        #pragma unroll
        for (int kk = 0; kk < 4; kk++) {
            int k = k4 * 4 + kk;
            ulonglong2 wv = *(const ulonglong2*)&g_WhT[k * 128 + lane * 4];
            #pragma unroll
            for (int g = 0; g < 4; g++) {
                float x = (&xq[g].x)[kk];
                ull xx = pack2(x, x);
                fma2(acc[g][0], xx, wv.x); fma2(acc[g][1], xx, wv.y);
            }
        }
    }
    #pragma unroll
    for (int g = 0; g < 4; g++) {
        int n = nbase + n0 + g;
        if (n < NNODE) {
            float inv = 1.f / sqrtf(g_deg[n] + 1e-4f);
            float2 r0 = unpack2(acc[g][0]), r1 = unpack2(acc[g][1]);
            float4 res = make_float4(r0.x * inv, r0.y * inv, r1.x * inv, r1.y * inv);
            *(float4*)&out[(size_t)n * 128 + lane * 4] = res;
        }
    }
}

// ---------------- launch ---------------------------------------------------------
extern "C" void kernel_launch(void* const* d_in, const int* in_sizes, int n_in,
                              void* d_out, int out_size) {
    // Inputs (setup_inputs order): q_sub, q_rel, hidden, edges, [n_node],
    // rela_embed, Ws_W, Wr_W, Wqr_W, Wqr_b, walpha_W, gateW_W, gateW_b,
    // ht_W, ht_b, Wh_W. Scalar n_node may or may not be materialized.
    int s = (n_in >= 16) ? 0 : -1;   // shift when n_node is materialized
    const void*  q_rel  =               d_in[1];
    const float* hidden = (const float*)d_in[2];
    const void*  edges  =               d_in[3];
    const float* rela   = (const float*)d_in[5 + s];
    const float* Ws     = (const float*)d_in[6 + s];
    const float* Wr     = (const float*)d_in[7 + s];
    const float* Wqr    = (const float*)d_in[8 + s];
    const float* Wqrb   = (const float*)d_in[9 + s];
    const float* walpha = (const float*)d_in[10 + s];
    const float* gateW  = (const float*)d_in[11 + s];
    const float* gb     = (const float*)d_in[12 + s];
    const float* htW    = (const float*)d_in[13 + s];
    const float* htb    = (const float*)d_in[14 + s];
    const float* Wh     = (const float*)d_in[15 + s];

    long long nE = (long long)in_sizes[3] / 7;
    const int SMEM_EDGE = (128 * VSTRIDE + EB * 128) * 4 + EB * 4 * 4 + EB * 4 + 64 * 4;

    cudaFuncSetAttribute(k_edge, cudaFuncAttributeMaxDynamicSharedMemorySize, SMEM_EDGE);

    k_setup<<<512, 256>>>((const int*)edges, gateW, htW, Ws, Wr, Wqr, Wh);
    k_pre<<<VOCABN + NQ, 128>>>(rela, htb, q_rel, gb, Wqrb);
    k_node<<<(NNODE + 31) / 32, 256>>>(hidden);
    int nb = (int)((nE + EB - 1) / EB);
    k_edge<<<nb, 256, SMEM_EDGE>>>(edges, hidden, walpha, nE);
    k_final<<<(NNODE + 31) / 32, 256>>>((float*)d_out);
}

// round 13
// speedup vs baseline: 1.0165x; 1.0165x over previous
#include <cuda_runtime.h>
#include <math.h>

#define NNODE 50000
#define VOCABN 401
#define NQ 64
#define EB 64
#define VSTRIDE 68

// ---------------- scratch (device globals: no allocation allowed) -------------
__device__ int   g_is64;                                   // index dtype flag (edges/q_rel)
__device__ __align__(16) float g_NG[NNODE * 256];          // hidden @ G3^T
__device__ __align__(16) float g_NW[NNODE * 64];           // hidden @ Ws^T
__device__ __align__(16) float g_RG[VOCABN * 256];         // rela @ G1^T
__device__ __align__(16) float g_RH[VOCABN * 128];         // rela @ H1^T + ht_b
__device__ __align__(16) float g_RW[VOCABN * 64];          // rela @ Wr^T
__device__ __align__(16) float g_QG[NQ * 256];             // hqr @ G2^T + gate_b
__device__ __align__(16) float g_QW[NQ * 64];              // hqr @ Wqr^T + Wqr_b
__device__ __align__(16) float g_GWT[384 * 256];           // gateW^T [c][j]
__device__ __align__(16) float g_HTT[256 * 128];           // ht_W^T  [c][j] (rows 128.. = H2T)
__device__ __align__(16) float g_WsT[128 * 64];
__device__ __align__(16) float g_WrT[128 * 64];
__device__ __align__(16) float g_WqrT[128 * 64];
__device__ __align__(16) float g_WhT[128 * 128];
__device__ __align__(16) float g_agg[NNODE * 128];
__device__ float g_deg[NNODE];

// Fast-math-independent transcendentals (MUFU path regardless of nvcc flags).
__device__ __forceinline__ float sigmoidf_(float x) {
    return __fdividef(1.f, 1.f + __expf(-x));
}
__device__ __forceinline__ float tanhf_(float x) {
    float t = __expf(2.f * x);
    return 1.f - __fdividef(2.f, t + 1.f);
}

// ---- packed f32x2 helpers (fma.rn.f32x2: sm_100+ only, 2x fp32 FMA rate) ----
typedef unsigned long long ull;
__device__ __forceinline__ void fma2(ull& acc, ull a, ull b) {
    asm("fma.rn.f32x2 %0, %1, %2, %0;" : "+l"(acc) : "l"(a), "l"(b));
}
__device__ __forceinline__ ull pack2(float x, float y) {
    ull r; asm("mov.b64 %0, {%1, %2};" : "=l"(r) : "f"(x), "f"(y)); return r;
}
__device__ __forceinline__ float2 unpack2(ull v) {
    float2 r; asm("mov.b64 {%0, %1}, %2;" : "=f"(r.x), "=f"(r.y) : "l"(v)); return r;
}
// Fire-and-forget global float add (guaranteed REDG, no return round-trip).
__device__ __forceinline__ void red_add(float* p, float v) {
    asm volatile("red.global.add.f32 [%0], %1;" :: "l"(p), "f"(v) : "memory");
}

// ---------------- setup: dtype detect + zero + weight transposes ----------------
__global__ void k_setup(const int* __restrict__ ew,
                        const float* __restrict__ gateW, const float* __restrict__ htW,
                        const float* __restrict__ Ws, const float* __restrict__ Wr,
                        const float* __restrict__ Wqr, const float* __restrict__ Wh) {
    if (blockIdx.x == 0) {
        __shared__ int any;
        if (threadIdx.x == 0) any = 0;
        __syncthreads();
        for (int i = threadIdx.x; i < 1024; i += blockDim.x)
            if (ew[2 * i + 1] != 0) any = 1;
        __syncthreads();
        if (threadIdx.x == 0) g_is64 = (any == 0) ? 1 : 0;
    }
    int i0 = blockIdx.x * blockDim.x + threadIdx.x;
    int st = gridDim.x * blockDim.x;
    for (int i = i0; i < NNODE * 128; i += st) g_agg[i] = 0.f;
    for (int i = i0; i < NNODE; i += st) g_deg[i] = 0.f;
    for (int x = i0; x < 384 * 256; x += st) { int c = x >> 8, j = x & 255; g_GWT[x] = gateW[j * 384 + c]; }
    for (int x = i0; x < 256 * 128; x += st) { int c = x >> 7, j = x & 127; g_HTT[x] = htW[j * 256 + c]; }
    for (int x = i0; x < 128 * 64;  x += st) { int k = x >> 6, j = x & 63;
        g_WsT[x] = Ws[j * 128 + k]; g_WrT[x] = Wr[j * 128 + k]; g_WqrT[x] = Wqr[j * 128 + k]; }
    for (int x = i0; x < 128 * 128; x += st) { int k = x >> 7, j = x & 127; g_WhT[x] = Wh[j * 128 + k]; }
}

// ------- merged per-vocab (blocks 0..400) + per-query (blocks 401..464) --------
__global__ void k_pre(const float* __restrict__ rela, const float* __restrict__ htb,
                      const void* __restrict__ q_rel, const float* __restrict__ gb,
                      const float* __restrict__ wqrb) {
    __shared__ float row[128];
    int tid = threadIdx.x;
    if (blockIdx.x < VOCABN) {
        int v = blockIdx.x;
        row[tid] = rela[v * 128 + tid];
        __syncthreads();
        float a0 = 0.f, a1 = 0.f, ah = htb[tid];
        #pragma unroll 4
        for (int k = 0; k < 128; k++) {
            float x = row[k];
            a0 += x * g_GWT[k * 256 + tid];
            a1 += x * g_GWT[k * 256 + 128 + tid];
            ah += x * g_HTT[k * 128 + tid];
        }
        g_RG[v * 256 + tid] = a0;
        g_RG[v * 256 + 128 + tid] = a1;
        g_RH[v * 128 + tid] = ah;
        if (tid < 64) {
            float aw = 0.f;
            #pragma unroll 4
            for (int k = 0; k < 128; k++) aw += row[k] * g_WrT[k * 64 + tid];
            g_RW[v * 64 + tid] = aw;
        }
    } else {
        int r = blockIdx.x - VOCABN;
        int q = g_is64 ? (int)((const long long*)q_rel)[r] : ((const int*)q_rel)[r];
        row[tid] = rela[q * 128 + tid];
        __syncthreads();
        float a0 = gb[tid], a1 = gb[128 + tid];
        #pragma unroll 4
        for (int k = 0; k < 128; k++) {
            float x = row[k];
            a0 += x * g_GWT[(128 + k) * 256 + tid];
            a1 += x * g_GWT[(128 + k) * 256 + 128 + tid];
        }
        g_QG[r * 256 + tid] = a0;
        g_QG[r * 256 + 128 + tid] = a1;
        if (tid < 64) {
            float aw = wqrb[tid];
            #pragma unroll 4
            for (int k = 0; k < 128; k++) aw += row[k] * g_WqrT[k * 64 + tid];
            g_QW[r * 64 + tid] = aw;
        }
    }
}

// ------- per-node precompute: NG = hidden@G3^T, NW = hidden@Ws^T ---------------
__global__ void __launch_bounds__(256) k_node(const float* __restrict__ hidden) {
    __shared__ float sx[32][128];
    int tid = threadIdx.x;
    int w = tid >> 5, lane = tid & 31;
    int nbase = blockIdx.x * 32;
    for (int i = tid; i < 32 * 32; i += 256) {
        int nn = i >> 5, q = i & 31;
        if (nbase + nn < NNODE)
            *(float4*)&sx[nn][q * 4] = *(const float4*)&hidden[(size_t)(nbase + nn) * 128 + q * 4];
    }
    __syncthreads();
    int n0 = w * 4;
    ull acc[4][5];
    #pragma unroll
    for (int g = 0; g < 4; g++)
        #pragma unroll
        for (int a = 0; a < 5; a++) acc[g][a] = 0ull;

    for (int k4 = 0; k4 < 32; k4++) {
        float4 xq[4];
        #pragma unroll
        for (int g = 0; g < 4; g++) xq[g] = *(const float4*)&sx[n0 + g][k4 * 4];
        #pragma unroll
        for (int kk = 0; kk < 4; kk++) {
            int k = k4 * 4 + kk;
            ulonglong2 g0 = *(const ulonglong2*)&g_GWT[(256 + k) * 256 + lane * 4];
            ulonglong2 g1 = *(const ulonglong2*)&g_GWT[(256 + k) * 256 + 128 + lane * 4];
            ull ws = *(const ull*)&g_WsT[k * 64 + lane * 2];
            #pragma unroll
            for (int g = 0; g < 4; g++) {
                float x = (&xq[g].x)[kk];
                ull xx = pack2(x, x);
                fma2(acc[g][0], xx, g0.x); fma2(acc[g][1], xx, g0.y);
                fma2(acc[g][2], xx, g1.x); fma2(acc[g][3], xx, g1.y);
                fma2(acc[g][4], xx, ws);
            }
        }
    }
    #pragma unroll
    for (int g = 0; g < 4; g++) {
        int n = nbase + n0 + g;
        if (n < NNODE) {
            *(ulonglong2*)&g_NG[(size_t)n * 256 + lane * 4]       = make_ulonglong2(acc[g][0], acc[g][1]);
            *(ulonglong2*)&g_NG[(size_t)n * 256 + 128 + lane * 4] = make_ulonglong2(acc[g][2], acc[g][3]);
            *(ull*)&g_NW[(size_t)n * 64 + lane * 2] = acc[g][4];
        }
    }
}

// ---------------- fused edge kernel ---------------------------------------------
// R12 profile: fma 31%, L1 50%, L2 15%, occ 22%, issue 32% => latency/occupancy
// bound, not memory bound. Fix: EB 96->64, VSTRIDE 68, Phase-B tile 4e x 8j over
// ALL 256 threads (16x16) => ~70 regs, 69 KB smem => 3 CTAs/SM (24 warps).
// Phase A: 8 warps x 2 groups of 4 edges (12+ gathers in flight, STS.128 V).
// Phase B: 64x128x128 GEMM, fma.rn.f32x2, H2T streamed from global (L1-hot).
// Phase C: tanh + GRU blend + sigmoid(alpha) scale + red.global.add.v4 scatter.
__global__ void __launch_bounds__(256, 3)
k_edge(const void* __restrict__ edges, const float* __restrict__ hidden,
       const float* __restrict__ walpha, long long nE) {
    extern __shared__ float smem[];
    float* sVT  = smem;                       // [128 k][VSTRIDE] V^T (padded e stride)
    float* sU   = sVT + 128 * VSTRIDE;        // [64 e][128 k] update gate
    int*   sIdx = (int*)(sU + EB * 128);      // [64 e][4] = {ridx, rel, sub, obj}
    float* sSig = (float*)(sIdx + EB * 4);    // [64 e]
    float* sWa  = sSig + EB;                  // [64] walpha staged

    int tid = threadIdx.x;
    long long base = (long long)blockIdx.x * EB;
    int is64 = g_is64;

    if (tid < 64) sWa[tid] = walpha[tid];
    // cooperative edge-index load (one field per thread)
    {
        int i = tid;  // EB*4 = 256 = blockDim
        int e = i >> 2, f = i & 3;
        long long ge = base + e;
        int v;
        if (ge < nE) {
            int col = (f == 0) ? 0 : (f == 1) ? 2 : (f == 2) ? 4 : 5;
            if (is64) v = (int)((const long long*)edges)[ge * 7 + col];
            else      v = ((const int*)edges)[ge * 7 + col];
        } else v = (f == 3) ? -1 : 0;
        sIdx[i] = v;
    }
    __syncthreads();

    int w = tid >> 5, lane = tid & 31;
    #pragma unroll
    for (int g4 = 0; g4 < 2; g4++) {
        int e0 = w * 8 + g4 * 4;
        int ridx[4], rel[4], sub[4], obj[4];
        #pragma unroll
        for (int g = 0; g < 4; g++) {
            ridx[g] = sIdx[(e0 + g) * 4 + 0];
            rel[g]  = sIdx[(e0 + g) * 4 + 1];
            sub[g]  = sIdx[(e0 + g) * 4 + 2];
            obj[g]  = sIdx[(e0 + g) * 4 + 3];
        }
        float ap[4] = {0.f, 0.f, 0.f, 0.f};
        #pragma unroll
        for (int p = 0; p < 4; p++) {
            int k = p * 32 + lane;
            float4 v;
            float* vv = &v.x;
            #pragma unroll
            for (int g = 0; g < 4; g++) {
                if (obj[g] >= 0) {
                    float gu = g_NG[sub[g] * 256 + k]       + g_RG[rel[g] * 256 + k]       + g_QG[ridx[g] * 256 + k];
                    float gr = g_NG[sub[g] * 256 + 128 + k] + g_RG[rel[g] * 256 + 128 + k] + g_QG[ridx[g] * 256 + 128 + k];
                    float u  = sigmoidf_(gu);
                    float r  = sigmoidf_(gr);
                    float hs = hidden[sub[g] * 128 + k];
                    vv[g] = r * hs;
                    sU[(e0 + g) * 128 + k] = u;
                    if (p < 2) {
                        float pre = g_NW[sub[g] * 64 + k] + g_RW[rel[g] * 64 + k] + g_QW[ridx[g] * 64 + k];
                        float lr = pre > 0.f ? pre : 0.01f * pre;
                        ap[g] += lr * sWa[k];
                    }
                } else {
                    vv[g] = 0.f;
                    sU[(e0 + g) * 128 + k] = 0.f;
                }
            }
            *(float4*)&sVT[k * VSTRIDE + e0] = v;   // conflict-free STS.128
        }
        #pragma unroll
        for (int g = 0; g < 4; g++) {
            #pragma unroll
            for (int o = 16; o; o >>= 1) ap[g] += __shfl_xor_sync(0xffffffffu, ap[g], o);
        }
        if (lane == 0) {
            #pragma unroll
            for (int g = 0; g < 4; g++) {
                if (obj[g] >= 0) {
                    sSig[e0 + g] = sigmoidf_(ap[g]);
                    red_add(&g_deg[obj[g]], 1.f);
                } else sSig[e0 + g] = 0.f;
            }
        }
    }
    __syncthreads();

    // Phase B: candpre[e][j] = sum_k V[e][k] * H2T[k][j]
    // 16 tx (j) x 16 ty (e), 4e x 8j tile per thread, ALL 256 threads.
    {
        int tx = tid & 15, ty = tid >> 4;
        int j0 = tx * 8, e0 = ty * 4;
        const float* H2T = g_HTT + 128 * 128;
        ull accp[4][4];
        #pragma unroll
        for (int i = 0; i < 4; i++)
            #pragma unroll
            for (int j = 0; j < 4; j++) accp[i][j] = 0ull;

        #pragma unroll 4
        for (int k = 0; k < 128; k++) {
            ulonglong2 b01 = *(const ulonglong2*)&H2T[k * 128 + j0];
            ulonglong2 b23 = *(const ulonglong2*)&H2T[k * 128 + j0 + 4];
            float4 a = *(const float4*)&sVT[k * VSTRIDE + e0];
            const float* av = &a.x;
            #pragma unroll
            for (int i = 0; i < 4; i++) {
                ull a2 = pack2(av[i], av[i]);
                fma2(accp[i][0], a2, b01.x);
                fma2(accp[i][1], a2, b01.y);
                fma2(accp[i][2], a2, b23.x);
                fma2(accp[i][3], a2, b23.y);
            }
        }

        // Phase C
        #pragma unroll
        for (int i = 0; i < 4; i++) {
            int e = e0 + i;
            int obj = sIdx[e * 4 + 3];
            if (obj < 0) continue;
            int rel = sIdx[e * 4 + 1], sub = sIdx[e * 4 + 2];
            float sg = sSig[e];
            #pragma unroll
            for (int h = 0; h < 2; h++) {
                int j = j0 + h * 4;
                float2 c0 = unpack2(accp[i][h * 2]);
                float2 c1 = unpack2(accp[i][h * 2 + 1]);
                float4 rh = *(const float4*)&g_RH[rel * 128 + j];
                float4 hv = *(const float4*)&hidden[sub * 128 + j];
                float4 uv = *(const float4*)&sU[e * 128 + j];
                float o0 = sg * ((1.f - uv.x) * hv.x + uv.x * tanhf_(c0.x + rh.x));
                float o1 = sg * ((1.f - uv.y) * hv.y + uv.y * tanhf_(c0.y + rh.y));
                float o2 = sg * ((1.f - uv.z) * hv.z + uv.z * tanhf_(c1.x + rh.z));
                float o3 = sg * ((1.f - uv.w) * hv.w + uv.w * tanhf_(c1.y + rh.w));
                float* p = g_agg + (size_t)obj * 128 + j;
                asm volatile("red.global.add.v4.f32 [%0], {%1,%2,%3,%4};"
                             :: "l"(p), "f"(o0), "f"(o1), "f"(o2), "f"(o3) : "memory");
            }
        }
    }
}

// ------- final: out = (agg @ Wh^T) / sqrt(deg+1e-4), 4 nodes per warp -----------
__global__ void __launch_bounds__(256) k_final(float* __restrict__ out) {
    __shared__ float sx[32][128];
    int tid = threadIdx.x;
    int w = tid >> 5, lane = tid & 31;
    int nbase = blockIdx.x * 32;
    for (int i = tid; i < 32 * 32; i += 256) {
        int nn = i >> 5, q = i & 31;
        if (nbase + nn < NNODE)
            *(float4*)&sx[nn][q * 4] = *(const float4*)&g_agg[(size_t)(nbase + nn) * 128 + q * 4];
    }
    __syncthreads();
    int n0 = w * 4;
    ull acc[4][2];
    #pragma unroll
    for (int g = 0; g < 4; g++) { acc[g][0] = 0ull; acc[g][1] = 0ull; }

    for (int k4 = 0; k4 < 32; k4++) {
        float4 xq[4];
        #pragma unroll
        for (int g = 0; g < 4; g++) xq[g] = *(const float4*)&sx[n0 + g][k4 * 4];
        #pragma unroll
        for (int kk = 0; kk < 4; kk++) {
            int k = k4 * 4 + kk;
            ulonglong2 wv = *(const ulonglong2*)&g_WhT[k * 128 + lane * 4];
            #pragma unroll
            for (int g = 0; g < 4; g++) {
                float x = (&xq[g].x)[kk];
                ull xx = pack2(x, x);
                fma2(acc[g][0], xx, wv.x); fma2(acc[g][1], xx, wv.y);
            }
        }
    }
    #pragma unroll
    for (int g = 0; g < 4; g++) {
        int n = nbase + n0 + g;
        if (n < NNODE) {
            float inv = 1.f / sqrtf(g_deg[n] + 1e-4f);
            float2 r0 = unpack2(acc[g][0]), r1 = unpack2(acc[g][1]);
            float4 res = make_float4(r0.x * inv, r0.y * inv, r1.x * inv, r1.y * inv);
            *(float4*)&out[(size_t)n * 128 + lane * 4] = res;
        }
    }
}

// ---------------- launch ---------------------------------------------------------
extern "C" void kernel_launch(void* const* d_in, const int* in_sizes, int n_in,
                              void* d_out, int out_size) {
    int s = (n_in >= 16) ? 0 : -1;   // shift when n_node is materialized
    const void*  q_rel  =               d_in[1];
    const float* hidden = (const float*)d_in[2];
    const void*  edges  =               d_in[3];
    const float* rela   = (const float*)d_in[5 + s];
    const float* Ws     = (const float*)d_in[6 + s];
    const float* Wr     = (const float*)d_in[7 + s];
    const float* Wqr    = (const float*)d_in[8 + s];
    const float* Wqrb   = (const float*)d_in[9 + s];
    const float* walpha = (const float*)d_in[10 + s];
    const float* gateW  = (const float*)d_in[11 + s];
    const float* gb     = (const float*)d_in[12 + s];
    const float* htW    = (const float*)d_in[13 + s];
    const float* htb    = (const float*)d_in[14 + s];
    const float* Wh     = (const float*)d_in[15 + s];

    long long nE = (long long)in_sizes[3] / 7;
    const int SMEM_EDGE = (128 * VSTRIDE + EB * 128) * 4 + EB * 4 * 4 + EB * 4 + 64 * 4;

    cudaFuncSetAttribute(k_edge, cudaFuncAttributeMaxDynamicSharedMemorySize, SMEM_EDGE);

    k_setup<<<512, 256>>>((const int*)edges, gateW, htW, Ws, Wr, Wqr, Wh);
    k_pre<<<VOCABN + NQ, 128>>>(rela, htb, q_rel, gb, Wqrb);
    k_node<<<(NNODE + 31) / 32, 256>>>(hidden);
    int nb = (int)((nE + EB - 1) / EB);
    k_edge<<<nb, 256, SMEM_EDGE>>>(edges, hidden, walpha, nE);
    k_final<<<(NNODE + 31) / 32, 256>>>((float*)d_out);
}